// round 11
// baseline (speedup 1.0000x reference)
#include <cuda_runtime.h>
#include <cuda_bf16.h>
#include <cstdint>

// Problem constants (fixed by the reference)
#define N_COLS  22
#define N_PAIRS 231
#define EMB     12
#define DVEC    64
#define N_PRIM  5
#define COMBO2  (EMB * EMB * 2)   // 288 floats per pair in the LUT
#define NCHUNK  8                 // pair-dimension split for kernel 2
#define CHUNKSZ ((N_PAIRS + NCHUNK - 1) / NCHUNK)   // 29

#define LUT_WARPS (N_PAIRS * EMB)       // 2772
#define A_WARPS   (N_COLS * EMB)        // 264: one per (column, emb)
#define K1_WARPS  (LUT_WARPS + A_WARPS) // 3036
#define K1_BLOCKS ((K1_WARPS + 7) / 8)  // 380

// Host-built index tables, passed by value (constant bank, 1.4 KB)
struct Tabs {
    uchar2 ij[N_PAIRS];          // pair -> (i, j)
    unsigned short cp[N_COLS][N_COLS - 1];  // column -> 21 x (pair | side<<8)
};

// Scratch (persistent __device__ globals; overwritten every replay)
__device__ __align__(16) float  g_T[N_PAIRS * COMBO2];  // non-separable LUT
__device__ __align__(16) float  g_A[N_COLS * EMB * 2];  // separable column table
__device__ unsigned char        g_sep[N_PAIRS];         // 1 = separable pair

// ---------------------------------------------------------------------------
// Kernel 1: two roles by global warp id.
//  warps [0, 2772): LUT for pair p = w/12, fi = w%12. Separable pairs (k=0
//    add, k=4 concat) write g_sep and exit; k in {1,2,3} compute the 12-entry
//    fj row via float4 loads + 16-lane shuffle reductions (no SMEM, no syncs).
//  warps [2772, 3036): A-builder, warp per (c, e):
//    A[c][e][o] = sum over the 21 pairs containing c (separable only) of
//    dot(w_side, tables[c][e]).  Deterministic fixed-order loop, no atomics.
// Also zero-initializes out[] (poisoned by harness) for kernel 2's atomics.
// ---------------------------------------------------------------------------
__global__ __launch_bounds__(256)
void build_lut_kernel(const float* __restrict__ tables,
                      const float* __restrict__ Wsmall,
                      const float* __restrict__ Wconcat,
                      const float* __restrict__ aw,
                      float* __restrict__ out, int outN,
                      const Tabs tabs)
{
    // zero the output buffer
    {
        const int gz = blockIdx.x * 256 + threadIdx.x;
        if (gz < outN) out[gz] = 0.0f;
    }

    const int gwarp = (blockIdx.x * 256 + threadIdx.x) >> 5;
    const int lane  = threadIdx.x & 31;
    const int half  = lane >> 4;         // 0/1 -> output o
    const int hl    = lane & 15;         // lane within half (d-quad)
    const float4* __restrict__ t4 = (const float4*)tables;

    if (gwarp < LUT_WARPS) {
        // ---------------- LUT role ----------------
        const int p  = gwarp / EMB;
        const int fi = gwarp % EMB;
        const int i  = tabs.ij[p].x;
        const int j  = tabs.ij[p].y;

        // primitive via one ballot (arch_weights is exact one-hot 0/1)
        const bool hot = (lane < N_PRIM) && (__ldg(&aw[p * N_PRIM + lane]) > 0.5f);
        const int  k   = __ffs(__ballot_sync(0xffffffffu, hot)) - 1;

        const bool sep = (k == 0) || (k == 4);
        if (fi == 0 && lane == 0) g_sep[p] = sep ? 1 : 0;
        if (sep) return;                 // handled by the A-builder

        const float4 Pi = __ldg(&t4[(i * EMB + fi) * (DVEC / 4) + hl]);
        const float4* __restrict__ ws = (const float4*)(Wsmall + (p * 4 + k) * 2 * DVEC);
        const float4 w0 = __ldg(&ws[hl]);        // o=0
        const float4 w1 = __ldg(&ws[16 + hl]);   // o=1

        float2* __restrict__ T2 = (float2*)g_T;
#pragma unroll
        for (int t = 0; t < 6; ++t) {
            const int fj = t * 2 + half;
            const float4 Q = __ldg(&t4[(j * EMB + fj) * (DVEC / 4) + hl]);
            float4 z;
            if (k == 1)      { z.x = Pi.x * Q.x; z.y = Pi.y * Q.y; z.z = Pi.z * Q.z; z.w = Pi.w * Q.w; }
            else if (k == 2) { z.x = fmaxf(Pi.x, Q.x); z.y = fmaxf(Pi.y, Q.y); z.z = fmaxf(Pi.z, Q.z); z.w = fmaxf(Pi.w, Q.w); }
            else             { z.x = fminf(Pi.x, Q.x); z.y = fminf(Pi.y, Q.y); z.z = fminf(Pi.z, Q.z); z.w = fminf(Pi.w, Q.w); }

            float s0 = z.x * w0.x + z.y * w0.y + z.z * w0.z + z.w * w0.w;
            float s1 = z.x * w1.x + z.y * w1.y + z.z * w1.z + z.w * w1.w;
#pragma unroll
            for (int off = 8; off; off >>= 1) {
                s0 += __shfl_xor_sync(0xffffffffu, s0, off);
                s1 += __shfl_xor_sync(0xffffffffu, s1, off);
            }
            if (hl == 0)
                T2[p * (EMB * EMB) + fi * EMB + fj] = make_float2(s0, s1);
        }
    } else if (gwarp < K1_WARPS) {
        // ---------------- A-builder role ----------------
        const int idx = gwarp - LUT_WARPS;   // 0..263
        const int c   = idx / EMB;
        const int e   = idx % EMB;
        const int o   = half;

        const float4 tv = __ldg(&t4[(c * EMB + e) * (DVEC / 4) + hl]);
        float acc = 0.0f;

#pragma unroll 3
        for (int n = 0; n < N_COLS - 1; ++n) {
            const unsigned short code = tabs.cp[c][n];
            const int p    = code & 255;
            const int side = code >> 8;          // 0 = c is i (P), 1 = c is j (Q)

            int k = 0;
#pragma unroll
            for (int t = 0; t < N_PRIM; ++t)
                if (__ldg(&aw[p * N_PRIM + t]) > 0.5f) k = t;

            if (k == 0) {
                const float4 w = __ldg((const float4*)(Wsmall + (p * 8 + o) * DVEC) + hl);
                acc += w.x * tv.x + w.y * tv.y + w.z * tv.z + w.w * tv.w;
            } else if (k == 4) {
                const float4 w = __ldg((const float4*)(Wconcat + (p * 2 + o) * (2 * DVEC) + side * DVEC) + hl);
                acc += w.x * tv.x + w.y * tv.y + w.z * tv.z + w.w * tv.w;
            }
        }
#pragma unroll
        for (int off = 8; off; off >>= 1)
            acc += __shfl_xor_sync(0xffffffffu, acc, off);
        if (hl == 0)
            g_A[(c * EMB + e) * 2 + o] = acc;
    }
}

// ---------------------------------------------------------------------------
// Kernel 2: out[b, :] += sum_{p in chunk, non-sep} T[p, f_i, f_j, :]
//           (+ chunk-0 blocks: sum_c A[c][f_c])
// grid = (B/32) x 8 chunks. lane = batch element; warp w strides its chunk's
// 29 pairs (warp-uniform skip of separable pairs). All 32 lanes gather inside
// ONE pair's 1.15 KB LUT region. Cross-warp SMEM reduce, then atomicAdd.
// ---------------------------------------------------------------------------
__global__ __launch_bounds__(256)
void accumulate_kernel(const int* __restrict__ feats,
                       float* __restrict__ out,
                       int B,
                       const Tabs tabs)
{
    __shared__ int           shf[32][N_COLS + 1];  // stride 23: conflict-free
    __shared__ float2        shred[8][32];
    __shared__ unsigned char ssep[CHUNKSZ];
    __shared__ float2        sA[N_COLS * EMB];     // 2.1 KB (chunk-0 use)

    const int tid   = threadIdx.x;
    const int lane  = tid & 31;
    const int warp  = tid >> 5;
    const int bbase = blockIdx.x * 32;
    const int p0    = blockIdx.y * CHUNKSZ;
    const int npair = min(N_PAIRS - p0, CHUNKSZ);
    const bool doA  = (blockIdx.y == 0);

    // cooperative staging: feats tile, sep flags, (chunk 0) A table
    for (int e = tid; e < 32 * N_COLS; e += 256) {
        const int row = e / N_COLS, col = e - row * N_COLS;
        const int b   = bbase + row;
        shf[row][col] = (b < B) ? feats[b * N_COLS + col] : 0;
    }
    if (tid < npair) ssep[tid] = g_sep[p0 + tid];
    if (doA) {
        const float2* __restrict__ A2 = (const float2*)g_A;
        for (int e = tid; e < N_COLS * EMB; e += 256) sA[e] = __ldg(&A2[e]);
    }
    __syncthreads();

    const float2* __restrict__ T2 = (const float2*)g_T;
    float ax = 0.0f, ay = 0.0f;

    // warp w handles chunk-local pairs w, w+8, ... (skip separable, uniform)
#pragma unroll 4
    for (int t = warp; t < npair; t += 8) {
        if (!ssep[t]) {
            const uchar2 ij = tabs.ij[p0 + t];   // constant bank, uniform
            const int fi = shf[lane][ij.x];
            const int fj = shf[lane][ij.y];
            const float2 v = __ldg(&T2[(p0 + t) * (EMB * EMB) + fi * EMB + fj]);
            ax += v.x;
            ay += v.y;
        }
    }

    // chunk-0 blocks fold in the separable column table (warp-split columns)
    if (doA) {
#pragma unroll
        for (int c = warp; c < N_COLS; c += 8) {
            const float2 a = sA[c * EMB + shf[lane][c]];
            ax += a.x;
            ay += a.y;
        }
    }

    shred[warp][lane] = make_float2(ax, ay);
    __syncthreads();

    if (warp == 0) {
        float sx = 0.0f, sy = 0.0f;
#pragma unroll
        for (int w = 0; w < 8; ++w) {
            const float2 s = shred[w][lane];
            sx += s.x;
            sy += s.y;
        }
        const int b = bbase + lane;
        if (b < B) {
            atomicAdd(&out[b * 2 + 0], sx);
            atomicAdd(&out[b * 2 + 1], sy);
        }
    }
}

// ---------------------------------------------------------------------------
// Launch: two kernels, single stream (proven fastest structure), graph-safe.
// Inputs (metadata order): feats(i32), tables(f32), W_small(f32),
//                          W_concat(f32), arch_weights(f32)
// ---------------------------------------------------------------------------
extern "C" void kernel_launch(void* const* d_in, const int* in_sizes, int n_in,
                              void* d_out, int out_size)
{
    const int*   feats   = (const int*)  d_in[0];
    const float* tables  = (const float*)d_in[1];
    const float* Wsmall  = (const float*)d_in[2];
    const float* Wconcat = (const float*)d_in[3];
    const float* aw      = (const float*)d_in[4];
    float*       out     = (float*)d_out;

    const int B = in_sizes[0] / N_COLS;   // 4096

    // host-side index tables -> constant-bank kernel param
    Tabs tabs;
    {
        int p = 0;
        int cnt[N_COLS] = {};
        for (int i = 0; i < N_COLS; ++i)
            for (int j = i + 1; j < N_COLS; ++j, ++p) {
                tabs.ij[p] = make_uchar2((unsigned char)i, (unsigned char)j);
                tabs.cp[i][cnt[i]++] = (unsigned short)(p);           // side 0: c == i
                tabs.cp[j][cnt[j]++] = (unsigned short)(p | (1 << 8)); // side 1: c == j
            }
    }

    build_lut_kernel<<<K1_BLOCKS, 256>>>(tables, Wsmall, Wconcat, aw,
                                         out, out_size, tabs);

    dim3 grid((B + 31) / 32, NCHUNK);     // 128 x 8 = 1024 blocks
    accumulate_kernel<<<grid, 256>>>(feats, out, B, tabs);
}

// round 12
// speedup vs baseline: 1.5831x; 1.5831x over previous
#include <cuda_runtime.h>
#include <cuda_bf16.h>
#include <cstdint>

// Problem constants (fixed by the reference)
#define N_COLS  22
#define N_PAIRS 231
#define EMB     12
#define DVEC    64
#define N_PRIM  5
#define COMBO2  (EMB * EMB * 2)   // 288 floats per pair in the LUT
#define NCHUNK  8                 // pair-dimension split for kernel 2
#define CHUNKSZ ((N_PAIRS + NCHUNK - 1) / NCHUNK)   // 29

// Pair index table, computed on host, passed by value (constant bank)
struct PairTab { uchar2 ij[N_PAIRS]; };

// Scratch: precomputed per-pair lookup table T[p][fi][fj][o]  (266 KB)
__device__ __align__(16) float g_T[N_PAIRS * COMBO2];

// ---------------------------------------------------------------------------
// Kernel 1: warp-per-(p, fi), quarter-warp layout. No SMEM, no __syncthreads.
// Lane q=lane>>3 (quarter), ql=lane&7 holds dims 8ql..8ql+7 (two float4).
// Quarter q computes fj = 4t+q for t=0..2; 3-level shuffle reduce (xor 4,2,1).
// Also zero-initializes out[] (poisoned by harness) for kernel 2's atomics.
// ---------------------------------------------------------------------------
__global__ __launch_bounds__(256)
void build_lut_kernel(const float* __restrict__ tables,
                      const float* __restrict__ Wsmall,
                      const float* __restrict__ Wconcat,
                      const float* __restrict__ aw,
                      float* __restrict__ out, int outN,
                      const PairTab tab)
{
    // zero the output buffer
    {
        const int gz = blockIdx.x * 256 + threadIdx.x;
        if (gz < outN) out[gz] = 0.0f;
    }

    const int gwarp = (blockIdx.x * 256 + threadIdx.x) >> 5;
    if (gwarp >= N_PAIRS * EMB) return;

    const int p    = gwarp / EMB;
    const int fi   = gwarp % EMB;
    const int lane = threadIdx.x & 31;
    const int q    = lane >> 3;          // quarter 0..3
    const int ql   = lane & 7;           // dim-octet within quarter

    const int i = tab.ij[p].x;
    const int j = tab.ij[p].y;

    // primitive via one ballot (arch_weights is exact one-hot 0/1)
    const bool hot = (lane < N_PRIM) && (__ldg(&aw[p * N_PRIM + lane]) > 0.5f);
    const int  k   = __ffs(__ballot_sync(0xffffffffu, hot)) - 1;

    const float4* __restrict__ t4 = (const float4*)tables;
    const float4 PiA = __ldg(&t4[(i * EMB + fi) * 16 + 2 * ql]);
    const float4 PiB = __ldg(&t4[(i * EMB + fi) * 16 + 2 * ql + 1]);

    float4 w0A, w0B, w1A, w1B;           // Q-side weights, o = 0 / 1
    float  pp0 = 0.0f, pp1 = 0.0f;       // reduced P-part for concat
    if (k == 4) {
        const float4* __restrict__ wc = (const float4*)(Wconcat + p * 2 * (2 * DVEC));
        const float4 a0A = __ldg(&wc[2 * ql]),      a0B = __ldg(&wc[2 * ql + 1]);      // o=0 P
        const float4 a1A = __ldg(&wc[32 + 2 * ql]), a1B = __ldg(&wc[33 + 2 * ql]);     // o=1 P
        w0A = __ldg(&wc[16 + 2 * ql]);  w0B = __ldg(&wc[17 + 2 * ql]);                 // o=0 Q
        w1A = __ldg(&wc[48 + 2 * ql]);  w1B = __ldg(&wc[49 + 2 * ql]);                 // o=1 Q
        pp0 = a0A.x * PiA.x + a0A.y * PiA.y + a0A.z * PiA.z + a0A.w * PiA.w
            + a0B.x * PiB.x + a0B.y * PiB.y + a0B.z * PiB.z + a0B.w * PiB.w;
        pp1 = a1A.x * PiA.x + a1A.y * PiA.y + a1A.z * PiA.z + a1A.w * PiA.w
            + a1B.x * PiB.x + a1B.y * PiB.y + a1B.z * PiB.z + a1B.w * PiB.w;
#pragma unroll
        for (int off = 4; off; off >>= 1) {
            pp0 += __shfl_xor_sync(0xffffffffu, pp0, off);
            pp1 += __shfl_xor_sync(0xffffffffu, pp1, off);
        }
    } else {
        const float4* __restrict__ ws = (const float4*)(Wsmall + (p * 4 + k) * 2 * DVEC);
        w0A = __ldg(&ws[2 * ql]);       w0B = __ldg(&ws[2 * ql + 1]);
        w1A = __ldg(&ws[16 + 2 * ql]);  w1B = __ldg(&ws[17 + 2 * ql]);
    }

    float2* __restrict__ T2 = (float2*)g_T;

#pragma unroll
    for (int t = 0; t < 3; ++t) {
        const int fj = t * 4 + q;
        const float4 QA = __ldg(&t4[(j * EMB + fj) * 16 + 2 * ql]);
        const float4 QB = __ldg(&t4[(j * EMB + fj) * 16 + 2 * ql + 1]);

        float4 zA, zB;
        if (k == 0)      { zA.x = PiA.x + QA.x; zA.y = PiA.y + QA.y; zA.z = PiA.z + QA.z; zA.w = PiA.w + QA.w;
                           zB.x = PiB.x + QB.x; zB.y = PiB.y + QB.y; zB.z = PiB.z + QB.z; zB.w = PiB.w + QB.w; }
        else if (k == 1) { zA.x = PiA.x * QA.x; zA.y = PiA.y * QA.y; zA.z = PiA.z * QA.z; zA.w = PiA.w * QA.w;
                           zB.x = PiB.x * QB.x; zB.y = PiB.y * QB.y; zB.z = PiB.z * QB.z; zB.w = PiB.w * QB.w; }
        else if (k == 2) { zA.x = fmaxf(PiA.x, QA.x); zA.y = fmaxf(PiA.y, QA.y); zA.z = fmaxf(PiA.z, QA.z); zA.w = fmaxf(PiA.w, QA.w);
                           zB.x = fmaxf(PiB.x, QB.x); zB.y = fmaxf(PiB.y, QB.y); zB.z = fmaxf(PiB.z, QB.z); zB.w = fmaxf(PiB.w, QB.w); }
        else if (k == 3) { zA.x = fminf(PiA.x, QA.x); zA.y = fminf(PiA.y, QA.y); zA.z = fminf(PiA.z, QA.z); zA.w = fminf(PiA.w, QA.w);
                           zB.x = fminf(PiB.x, QB.x); zB.y = fminf(PiB.y, QB.y); zB.z = fminf(PiB.z, QB.z); zB.w = fminf(PiB.w, QB.w); }
        else             { zA = QA; zB = QB; }   // concat: Q-part only

        float s0 = zA.x * w0A.x + zA.y * w0A.y + zA.z * w0A.z + zA.w * w0A.w
                 + zB.x * w0B.x + zB.y * w0B.y + zB.z * w0B.z + zB.w * w0B.w;
        float s1 = zA.x * w1A.x + zA.y * w1A.y + zA.z * w1A.z + zA.w * w1A.w
                 + zB.x * w1B.x + zB.y * w1B.y + zB.z * w1B.z + zB.w * w1B.w;
#pragma unroll
        for (int off = 4; off; off >>= 1) {
            s0 += __shfl_xor_sync(0xffffffffu, s0, off);
            s1 += __shfl_xor_sync(0xffffffffu, s1, off);
        }
        if (k == 4) { s0 += pp0; s1 += pp1; }

        if (ql == 0)
            T2[p * (EMB * EMB) + fi * EMB + fj] = make_float2(s0, s1);
    }
}

// ---------------------------------------------------------------------------
// Kernel 2: out[b, :] += sum_{p in chunk} T[p, f[i_p], f[j_p], :]
// grid = (NCHUNK, ntiles): bid = chunk + 8*tile, so same-SM co-resident
// blocks (bid stride 148, 148 mod 8 = 4) host only chunks {c, c+4} ->
// working set 2 x 33 KB of g_T fits L1 -> gathers upgrade from L2 to L1.
// lane = batch element; warp w strides its chunk's 29 pairs (<=4 unrolled
// independent gathers, all 32 lanes inside one pair's 1.15 KB region).
// Cross-warp SMEM reduce, then atomicAdd (out zeroed by kernel 1).
// ---------------------------------------------------------------------------
__global__ __launch_bounds__(256)
void accumulate_kernel(const int* __restrict__ feats,
                       float* __restrict__ out,
                       int B,
                       const PairTab tab)
{
    __shared__ int    shf[32][N_COLS + 1];   // stride 23: coprime with 32 banks
    __shared__ float2 shred[8][32];

    const int tid   = threadIdx.x;
    const int lane  = tid & 31;
    const int warp  = tid >> 5;
    const int bbase = blockIdx.y * 32;       // tile
    const int p0    = blockIdx.x * CHUNKSZ;  // chunk
    const int npair = min(N_PAIRS - p0, CHUNKSZ);

    // coalesced, cooperative load of this block's 32 feats rows
    for (int e = tid; e < 32 * N_COLS; e += 256) {
        const int row = e / N_COLS, col = e - row * N_COLS;
        const int b   = bbase + row;
        shf[row][col] = (b < B) ? feats[b * N_COLS + col] : 0;
    }
    __syncthreads();

    const float2* __restrict__ T2 = (const float2*)g_T;
    float ax = 0.0f, ay = 0.0f;

    // warp w handles chunk-local pairs w, w+8, ... (<= 4 independent gathers)
#pragma unroll 4
    for (int t = warp; t < npair; t += 8) {
        const uchar2 ij = tab.ij[p0 + t];        // constant bank, uniform
        const int fi = shf[lane][ij.x];
        const int fj = shf[lane][ij.y];
        const float2 v = __ldg(&T2[(p0 + t) * (EMB * EMB) + fi * EMB + fj]);
        ax += v.x;
        ay += v.y;
    }

    shred[warp][lane] = make_float2(ax, ay);
    __syncthreads();

    if (warp == 0) {
        float sx = 0.0f, sy = 0.0f;
#pragma unroll
        for (int w = 0; w < 8; ++w) {
            const float2 s = shred[w][lane];
            sx += s.x;
            sy += s.y;
        }
        const int b = bbase + lane;
        if (b < B) {
            atomicAdd(&out[b * 2 + 0], sx);
            atomicAdd(&out[b * 2 + 1], sy);
        }
    }
}

// ---------------------------------------------------------------------------
// Launch: two kernels, single stream (proven fastest structure), graph-safe.
// Inputs (metadata order): feats(i32), tables(f32), W_small(f32),
//                          W_concat(f32), arch_weights(f32)
// ---------------------------------------------------------------------------
extern "C" void kernel_launch(void* const* d_in, const int* in_sizes, int n_in,
                              void* d_out, int out_size)
{
    const int*   feats   = (const int*)  d_in[0];
    const float* tables  = (const float*)d_in[1];
    const float* Wsmall  = (const float*)d_in[2];
    const float* Wconcat = (const float*)d_in[3];
    const float* aw      = (const float*)d_in[4];
    float*       out     = (float*)d_out;

    const int B = in_sizes[0] / N_COLS;   // 4096

    // host-side triu(N_COLS, 1) pair table -> constant-bank kernel param
    PairTab tab;
    {
        int p = 0;
        for (int i = 0; i < N_COLS; ++i)
            for (int j = i + 1; j < N_COLS; ++j, ++p)
                tab.ij[p] = make_uchar2((unsigned char)i, (unsigned char)j);
    }

    const int k1_blocks = (N_PAIRS * EMB * 32 + 255) / 256;   // 347
    build_lut_kernel<<<k1_blocks, 256>>>(tables, Wsmall, Wconcat, aw,
                                         out, out_size, tab);

    dim3 grid(NCHUNK, (B + 31) / 32);     // 8 x 128 = 1024 blocks, chunk-major
    accumulate_kernel<<<grid, 256>>>(feats, out, B, tab);
}